// round 4
// baseline (speedup 1.0000x reference)
#include <cuda_runtime.h>
#include <cuda_bf16.h>
#include <cstddef>

// Problem constants
#define BATCH 4
#define C     64
#define H     512
#define W     512
#define LAT   256
#define TH    16
#define TW    16
#define SR    18      // tile + halo
#define CI    32      // input-channel chunk held in smem

// Scratch (module-load allocated, not runtime alloc)
__device__ float g_wm0[BATCH * C * 9 * C];
__device__ float g_wm1[BATCH * C * 9 * C];
__device__ float g_mid[(size_t)BATCH * C * H * W];

__device__ __forceinline__ int refl(int v) {
    return v < 0 ? -v : (v > H - 1 ? 2 * (H - 1) - v : v);
}

__device__ __forceinline__ void fma2(unsigned long long& acc,
                                     unsigned long long a,
                                     unsigned long long b) {
    asm("fma.rn.f32x2 %0, %1, %2, %0;" : "+l"(acc) : "l"(a), "l"(b));
}

__device__ __forceinline__ unsigned long long pack2(float x) {
    unsigned long long r;
    asm("mov.b64 %0, {%1, %1};" : "=l"(r) : "f"(x));
    return r;
}

// ---------------------------------------------------------------------------
// Prep: fold EqualLinear modulation + demodulation into per-batch weights.
//   s[b][i]   = 1 + sqrt(2/LAT) * <latent[b], mw[i]> + mb[i]
//   d[b][o]   = rsqrt( sum_i s^2 * wscale^2*sum_t w[o][i][t]^2 + 1e-5 )
//   Wm[b][i][t][o] = d[b][o] * s[b][i] * w[o][i][t] * wscale
// Layout: o contiguous (for paired LDS.64 in the conv).
// ---------------------------------------------------------------------------
template <int PASS>
__global__ void prep_kernel(const float* __restrict__ latent,
                            const float* __restrict__ w,
                            const float* __restrict__ mw,
                            const float* __restrict__ mb) {
    float* gwm = (PASS == 0) ? g_wm0 : g_wm1;
    __shared__ float s[C];
    __shared__ float d[C];
    const int b = blockIdx.x;
    const int t = threadIdx.x;
    const float lscale = 0.08838834764831845f;   // sqrt(2/256)
    const float wscale = 0.05892556509887896f;   // sqrt(2/576)

    if (t < C) {
        float acc = 0.f;
        const float* lb  = latent + b * LAT;
        const float* mwr = mw + t * LAT;
        #pragma unroll 4
        for (int l = 0; l < LAT; ++l) acc += lb[l] * mwr[l];
        s[t] = 1.f + acc * lscale + mb[t];
    }
    __syncthreads();
    if (t < C) {
        float acc = 0.f;
        for (int i = 0; i < C; ++i) {
            float wsq = 0.f;
            const float* wr = w + (t * C + i) * 9;
            #pragma unroll
            for (int k = 0; k < 9; ++k) { float v = wr[k]; wsq += v * v; }
            acc += s[i] * s[i] * wsq;
        }
        d[t] = rsqrtf(acc * wscale * wscale + 1e-5f);
    }
    __syncthreads();
    for (int idx = t; idx < C * 9 * C; idx += blockDim.x) {
        int o = idx & 63;
        int k = (idx >> 6) % 9;
        int i = idx / (9 * 64);
        gwm[b * C * 9 * C + idx] = d[o] * s[i] * w[(o * C + i) * 9 + k] * wscale;
    }
}

// ---------------------------------------------------------------------------
// Direct conv 3x3, reflect pad, + bias + leakyrelu(0.2)*sqrt(2).
// Block: 16x16 output tile, one batch item, all 64 output channels.
// 512 threads: t = og*128 + p ; og in 0..3 -> 16 output channels each;
//              p -> pixel (py, px) plus second pixel (py+8, px).
// Inner loop: broadcast LDS.64 weight pair + 2x fma.rn.f32x2 (FMA-pipe bound).
// ---------------------------------------------------------------------------
template <int PASS>
__global__ void __launch_bounds__(512, 1)
conv_kernel(const float* __restrict__ xin,
            const float* __restrict__ bias,
            float* __restrict__ xout) {
    const float* src = (PASS == 0) ? xin : g_mid;
    const float* wm  = (PASS == 0) ? g_wm0 : g_wm1;
    float* dst       = (PASS == 0) ? g_mid : xout;

    extern __shared__ float sm[];
    float* sx = sm;                    // [C][SR*SR]
    float* sw = sm + C * SR * SR;      // [CI*9*64]

    const int b  = blockIdx.z;
    const int y0 = blockIdx.y * TH;
    const int x0 = blockIdx.x * TW;
    const int t  = threadIdx.x;
    const int p  = t & 127;
    const int og = t >> 7;             // 0..3
    const int py = p >> 4;             // 0..7 (rows py and py+8)
    const int px = p & 15;
    const int obase = og * 16;

    const size_t plane = (size_t)H * W;
    const float* srcb = src + (size_t)b * C * plane;

    // Load input tile with reflect-pad halo
    for (int idx = t; idx < C * SR * SR; idx += 512) {
        int c   = idx / (SR * SR);
        int rem = idx - c * (SR * SR);
        int r   = rem / SR;
        int cc  = rem - r * SR;
        int gy  = refl(y0 + r - 1);
        int gx  = refl(x0 + cc - 1);
        sx[idx] = srcb[c * plane + (size_t)gy * W + gx];
    }

    unsigned long long accA[8], accB[8];
    #pragma unroll
    for (int q = 0; q < 8; ++q) { accA[q] = 0ull; accB[q] = 0ull; }

    for (int ch = 0; ch < C; ch += CI) {
        __syncthreads();
        const float* wsrc = wm + ((size_t)b * C + ch) * 9 * 64;
        for (int idx = t; idx < CI * 9 * 64; idx += 512) sw[idx] = wsrc[idx];
        __syncthreads();

        #pragma unroll 1
        for (int i = 0; i < CI; ++i) {
            const float* sxc = sx + (ch + i) * (SR * SR);
            #pragma unroll
            for (int tap = 0; tap < 9; ++tap) {
                const int ky = tap / 3;
                const int kx = tap - 3 * ky;
                float xa = sxc[(py + ky) * SR + px + kx];
                float xb = sxc[(py + 8 + ky) * SR + px + kx];
                unsigned long long xa2 = pack2(xa);
                unsigned long long xb2 = pack2(xb);
                const float* swp = sw + (i * 9 + tap) * 64 + obase;
                #pragma unroll
                for (int q = 0; q < 8; ++q) {
                    unsigned long long w2 =
                        *reinterpret_cast<const unsigned long long*>(swp + 2 * q);
                    fma2(accA[q], w2, xa2);
                    fma2(accB[q], w2, xb2);
                }
            }
        }
    }

    // Epilogue: + bias, leaky-relu * sqrt(2), store
    const float gain = 1.4142135623730951f;
    #pragma unroll
    for (int q = 0; q < 8; ++q) {
        const int o = obase + 2 * q;
        float v0 = __uint_as_float((unsigned)(accA[q] & 0xffffffffull));
        float v1 = __uint_as_float((unsigned)(accA[q] >> 32));
        float v2 = __uint_as_float((unsigned)(accB[q] & 0xffffffffull));
        float v3 = __uint_as_float((unsigned)(accB[q] >> 32));
        const float bo0 = bias[o], bo1 = bias[o + 1];
        v0 += bo0; v1 += bo1; v2 += bo0; v3 += bo1;
        v0 = (v0 >= 0.f ? v0 : 0.2f * v0) * gain;
        v1 = (v1 >= 0.f ? v1 : 0.2f * v1) * gain;
        v2 = (v2 >= 0.f ? v2 : 0.2f * v2) * gain;
        v3 = (v3 >= 0.f ? v3 : 0.2f * v3) * gain;
        float* d0 = dst + ((size_t)(b * C + o) * H + y0 + py) * W + x0 + px;
        float* d1 = dst + ((size_t)(b * C + o + 1) * H + y0 + py) * W + x0 + px;
        d0[0] = v0;
        d1[0] = v1;
        d0[(size_t)8 * W] = v2;
        d1[(size_t)8 * W] = v3;
    }
}

extern "C" void kernel_launch(void* const* d_in, const int* in_sizes, int n_in,
                              void* d_out, int out_size) {
    const float* x      = (const float*)d_in[0];
    const float* latent = (const float*)d_in[1];
    const float* w0     = (const float*)d_in[2];
    const float* b0     = (const float*)d_in[3];
    const float* mw0    = (const float*)d_in[4];
    const float* mb0    = (const float*)d_in[5];
    const float* w1     = (const float*)d_in[6];
    const float* b1     = (const float*)d_in[7];
    const float* mw1    = (const float*)d_in[8];
    const float* mb1    = (const float*)d_in[9];
    float* out = (float*)d_out;

    const int smem = (C * SR * SR + CI * 9 * 64) * 4;  // 156672 B
    cudaFuncSetAttribute(conv_kernel<0>,
                         cudaFuncAttributeMaxDynamicSharedMemorySize, smem);
    cudaFuncSetAttribute(conv_kernel<1>,
                         cudaFuncAttributeMaxDynamicSharedMemorySize, smem);

    prep_kernel<0><<<BATCH, 256>>>(latent, w0, mw0, mb0);
    prep_kernel<1><<<BATCH, 256>>>(latent, w1, mw1, mb1);

    dim3 grid(W / TW, H / TH, BATCH);
    conv_kernel<0><<<grid, 512, smem>>>(x, b0, nullptr);
    conv_kernel<1><<<grid, 512, smem>>>(nullptr, b1, out);
}

// round 5
// speedup vs baseline: 1.0537x; 1.0537x over previous
#include <cuda_runtime.h>
#include <cuda_bf16.h>
#include <cstddef>

// Problem constants
#define BATCH 4
#define C     64
#define H     512
#define W     512
#define LAT   256
#define TH    16
#define TW    16
#define SR    18      // tile + halo
#define CI    32      // input-channel chunk held in smem

// Scratch (module-load allocated, not runtime alloc)
__device__ float g_wm0[BATCH * C * 9 * C];
__device__ float g_wm1[BATCH * C * 9 * C];
__device__ float g_mid[(size_t)BATCH * C * H * W];

__device__ __forceinline__ int refl(int v) {
    return v < 0 ? -v : (v > H - 1 ? 2 * (H - 1) - v : v);
}

__device__ __forceinline__ void fma2(unsigned long long& acc,
                                     unsigned long long a,
                                     unsigned long long b) {
    asm("fma.rn.f32x2 %0, %1, %2, %0;" : "+l"(acc) : "l"(a), "l"(b));
}

__device__ __forceinline__ unsigned long long pack2(float x) {
    unsigned long long r;
    asm("mov.b64 %0, {%1, %1};" : "=l"(r) : "f"(x));
    return r;
}

// ---------------------------------------------------------------------------
// Prep: fold EqualLinear modulation + demodulation into per-batch weights.
//   s[b][i]   = 1 + sqrt(2/LAT) * <latent[b], mw[i]> + mb[i]
//   d[b][o]   = rsqrt( sum_i s^2 * wscale^2*sum_t w[o][i][t]^2 + 1e-5 )
//   Wm[b][i][t][o] = d[b][o] * s[b][i] * w[o][i][t] * wscale
// Layout: o contiguous (for paired LDS.64 in the conv).
// ---------------------------------------------------------------------------
template <int PASS>
__global__ void prep_kernel(const float* __restrict__ latent,
                            const float* __restrict__ w,
                            const float* __restrict__ mw,
                            const float* __restrict__ mb) {
    float* gwm = (PASS == 0) ? g_wm0 : g_wm1;
    __shared__ float s[C];
    __shared__ float d[C];
    const int b = blockIdx.x;
    const int t = threadIdx.x;
    const float lscale = 0.08838834764831845f;   // sqrt(2/256)
    const float wscale = 0.05892556509887896f;   // sqrt(2/576)

    if (t < C) {
        float acc = 0.f;
        const float* lb  = latent + b * LAT;
        const float* mwr = mw + t * LAT;
        #pragma unroll 4
        for (int l = 0; l < LAT; ++l) acc += lb[l] * mwr[l];
        s[t] = 1.f + acc * lscale + mb[t];
    }
    __syncthreads();
    if (t < C) {
        float acc = 0.f;
        for (int i = 0; i < C; ++i) {
            float wsq = 0.f;
            const float* wr = w + (t * C + i) * 9;
            #pragma unroll
            for (int k = 0; k < 9; ++k) { float v = wr[k]; wsq += v * v; }
            acc += s[i] * s[i] * wsq;
        }
        d[t] = rsqrtf(acc * wscale * wscale + 1e-5f);
    }
    __syncthreads();
    for (int idx = t; idx < C * 9 * C; idx += blockDim.x) {
        int o = idx & 63;
        int k = (idx >> 6) % 9;
        int i = idx / (9 * 64);
        gwm[b * C * 9 * C + idx] = d[o] * s[i] * w[(o * C + i) * 9 + k] * wscale;
    }
}

// ---------------------------------------------------------------------------
// Direct conv 3x3, reflect pad, + bias + leakyrelu(0.2)*sqrt(2).
// Block: 16x16 output tile, one batch item, all 64 output channels.
// 512 threads: t = og*128 + p ; og in 0..3 -> 16 output channels each;
//              p -> pixel (py, px) plus second pixel (py+8, px).
// Inner loop: broadcast LDS.64 weight pair + 2x fma.rn.f32x2 (FMA-pipe bound).
// ---------------------------------------------------------------------------
template <int PASS>
__global__ void __launch_bounds__(512, 1)
conv_kernel(const float* __restrict__ xin,
            const float* __restrict__ bias,
            float* __restrict__ xout) {
    const float* src = (PASS == 0) ? xin : g_mid;
    const float* wm  = (PASS == 0) ? g_wm0 : g_wm1;
    float* dst       = (PASS == 0) ? g_mid : xout;

    extern __shared__ float sm[];
    float* sx = sm;                    // [C][SR*SR]
    float* sw = sm + C * SR * SR;      // [CI*9*64]

    const int b  = blockIdx.z;
    const int y0 = blockIdx.y * TH;
    const int x0 = blockIdx.x * TW;
    const int t  = threadIdx.x;
    const int p  = t & 127;
    const int og = t >> 7;             // 0..3
    const int py = p >> 4;             // 0..7 (rows py and py+8)
    const int px = p & 15;
    const int obase = og * 16;

    const size_t plane = (size_t)H * W;
    const float* srcb = src + (size_t)b * C * plane;

    // Load input tile with reflect-pad halo
    for (int idx = t; idx < C * SR * SR; idx += 512) {
        int c   = idx / (SR * SR);
        int rem = idx - c * (SR * SR);
        int r   = rem / SR;
        int cc  = rem - r * SR;
        int gy  = refl(y0 + r - 1);
        int gx  = refl(x0 + cc - 1);
        sx[idx] = srcb[c * plane + (size_t)gy * W + gx];
    }

    unsigned long long accA[8], accB[8];
    #pragma unroll
    for (int q = 0; q < 8; ++q) { accA[q] = 0ull; accB[q] = 0ull; }

    for (int ch = 0; ch < C; ch += CI) {
        __syncthreads();
        const float* wsrc = wm + ((size_t)b * C + ch) * 9 * 64;
        for (int idx = t; idx < CI * 9 * 64; idx += 512) sw[idx] = wsrc[idx];
        __syncthreads();

        #pragma unroll 1
        for (int i = 0; i < CI; ++i) {
            const float* sxc = sx + (ch + i) * (SR * SR);
            #pragma unroll
            for (int tap = 0; tap < 9; ++tap) {
                const int ky = tap / 3;
                const int kx = tap - 3 * ky;
                float xa = sxc[(py + ky) * SR + px + kx];
                float xb = sxc[(py + 8 + ky) * SR + px + kx];
                unsigned long long xa2 = pack2(xa);
                unsigned long long xb2 = pack2(xb);
                const float* swp = sw + (i * 9 + tap) * 64 + obase;
                #pragma unroll
                for (int q = 0; q < 8; ++q) {
                    unsigned long long w2 =
                        *reinterpret_cast<const unsigned long long*>(swp + 2 * q);
                    fma2(accA[q], w2, xa2);
                    fma2(accB[q], w2, xb2);
                }
            }
        }
    }

    // Epilogue: + bias, leaky-relu * sqrt(2), store
    const float gain = 1.4142135623730951f;
    #pragma unroll
    for (int q = 0; q < 8; ++q) {
        const int o = obase + 2 * q;
        float v0 = __uint_as_float((unsigned)(accA[q] & 0xffffffffull));
        float v1 = __uint_as_float((unsigned)(accA[q] >> 32));
        float v2 = __uint_as_float((unsigned)(accB[q] & 0xffffffffull));
        float v3 = __uint_as_float((unsigned)(accB[q] >> 32));
        const float bo0 = bias[o], bo1 = bias[o + 1];
        v0 += bo0; v1 += bo1; v2 += bo0; v3 += bo1;
        v0 = (v0 >= 0.f ? v0 : 0.2f * v0) * gain;
        v1 = (v1 >= 0.f ? v1 : 0.2f * v1) * gain;
        v2 = (v2 >= 0.f ? v2 : 0.2f * v2) * gain;
        v3 = (v3 >= 0.f ? v3 : 0.2f * v3) * gain;
        float* d0 = dst + ((size_t)(b * C + o) * H + y0 + py) * W + x0 + px;
        float* d1 = dst + ((size_t)(b * C + o + 1) * H + y0 + py) * W + x0 + px;
        d0[0] = v0;
        d1[0] = v1;
        d0[(size_t)8 * W] = v2;
        d1[(size_t)8 * W] = v3;
    }
}

extern "C" void kernel_launch(void* const* d_in, const int* in_sizes, int n_in,
                              void* d_out, int out_size) {
    const float* x      = (const float*)d_in[0];
    const float* latent = (const float*)d_in[1];
    const float* w0     = (const float*)d_in[2];
    const float* b0     = (const float*)d_in[3];
    const float* mw0    = (const float*)d_in[4];
    const float* mb0    = (const float*)d_in[5];
    const float* w1     = (const float*)d_in[6];
    const float* b1     = (const float*)d_in[7];
    const float* mw1    = (const float*)d_in[8];
    const float* mb1    = (const float*)d_in[9];
    float* out = (float*)d_out;

    const int smem = (C * SR * SR + CI * 9 * 64) * 4;  // 156672 B
    cudaFuncSetAttribute(conv_kernel<0>,
                         cudaFuncAttributeMaxDynamicSharedMemorySize, smem);
    cudaFuncSetAttribute(conv_kernel<1>,
                         cudaFuncAttributeMaxDynamicSharedMemorySize, smem);

    prep_kernel<0><<<BATCH, 256>>>(latent, w0, mw0, mb0);
    prep_kernel<1><<<BATCH, 256>>>(latent, w1, mw1, mb1);

    dim3 grid(W / TW, H / TH, BATCH);
    conv_kernel<0><<<grid, 512, smem>>>(x, b0, nullptr);
    conv_kernel<1><<<grid, 512, smem>>>(nullptr, b1, out);
}

// round 7
// speedup vs baseline: 2.0787x; 1.9727x over previous
#include <cuda_runtime.h>
#include <cuda_bf16.h>
#include <cstdint>
#include <cstddef>

#define BATCH 4
#define C     64
#define H     512
#define Wd    512
#define LAT   256

#define TILE_W 16
#define TILE_H 8
#define HALO_W 18
#define HALO_H 10
#define ICP    68                       // padded ic stride (elems) -> 136B/pixel
#define PXB    (ICP * 2)                // 136
#define XTILE_B (HALO_W * HALO_H * PXB) // 24480
#define W_B     147456                  // 9 taps * 2 terms * 64oc * 128B
#define XHI_OFF W_B
#define XLO_OFF (W_B + XTILE_B)
#define SMEM_SZ (W_B + 2 * XTILE_B)     // 196416 <= 227KB

// Scratch
__device__ __nv_bfloat16 g_wA0[BATCH * 73728];   // pre-swizzled hi/lo weights
__device__ __nv_bfloat16 g_wA1[BATCH * 73728];
__device__ float g_mid[(size_t)BATCH * C * H * Wd];

__device__ __forceinline__ int refl(int v) {
    return v < 0 ? -v : (v > H - 1 ? 2 * (H - 1) - v : v);
}
__device__ __forceinline__ uint32_t smem_u32(const void* p) {
    uint32_t a;
    asm("{ .reg .u64 t; cvta.to.shared.u64 t, %1; cvt.u32.u64 %0, t; }" : "=r"(a) : "l"(p));
    return a;
}
__device__ __forceinline__ void ldmA(uint32_t* r, uint32_t addr) {
    asm volatile("ldmatrix.sync.aligned.m8n8.x4.shared.b16 {%0,%1,%2,%3}, [%4];"
                 : "=r"(r[0]), "=r"(r[1]), "=r"(r[2]), "=r"(r[3]) : "r"(addr));
}
__device__ __forceinline__ void mma16816(float* c, const uint32_t* a,
                                         uint32_t b0, uint32_t b1) {
    asm volatile("mma.sync.aligned.m16n8k16.row.col.f32.bf16.bf16.f32 "
                 "{%0,%1,%2,%3},{%4,%5,%6,%7},{%8,%9},{%0,%1,%2,%3};"
                 : "+f"(c[0]), "+f"(c[1]), "+f"(c[2]), "+f"(c[3])
                 : "r"(a[0]), "r"(a[1]), "r"(a[2]), "r"(a[3]), "r"(b0), "r"(b1));
}

// ---------------------------------------------------------------------------
// Prep: fold modulation + demod; emit bf16 hi/lo in ldmatrix-swizzled layout.
// Per batch: 18 tiles (tap-major, hi then lo) of 4096 bf16 = 73728 elems.
// Tile layout: elem(oc, ic) at oc*64 + (((ic>>3) ^ (oc&7))*8) + (ic&7).
// ---------------------------------------------------------------------------
template <int PASS>
__global__ void prep_kernel(const float* __restrict__ latent,
                            const float* __restrict__ w,
                            const float* __restrict__ mw,
                            const float* __restrict__ mb) {
    __nv_bfloat16* gw = (PASS == 0) ? g_wA0 : g_wA1;
    __shared__ float s[C];
    __shared__ float d[C];
    const int b = blockIdx.x;
    const int t = threadIdx.x;
    const float lscale = 0.08838834764831845f;   // sqrt(2/256)
    const float wscale = 0.05892556509887896f;   // sqrt(2/576)

    if (t < C) {
        float acc = 0.f;
        const float* lb  = latent + b * LAT;
        const float* mwr = mw + t * LAT;
        #pragma unroll 4
        for (int l = 0; l < LAT; ++l) acc += lb[l] * mwr[l];
        s[t] = 1.f + acc * lscale + mb[t];
    }
    __syncthreads();
    if (t < C) {
        float acc = 0.f;
        for (int i = 0; i < C; ++i) {
            float wsq = 0.f;
            const float* wr = w + (t * C + i) * 9;
            #pragma unroll
            for (int k = 0; k < 9; ++k) { float v = wr[k]; wsq += v * v; }
            acc += s[i] * s[i] * wsq;
        }
        d[t] = rsqrtf(acc * wscale * wscale + 1e-5f);
    }
    __syncthreads();
    for (int idx = t; idx < 9 * 64 * 64; idx += blockDim.x) {
        int ic  = idx & 63;
        int o   = (idx >> 6) & 63;
        int tap = idx >> 12;
        float v = d[o] * s[ic] * w[(o * 64 + ic) * 9 + tap] * wscale;
        __nv_bfloat16 hv = __float2bfloat16(v);
        __nv_bfloat16 lv = __float2bfloat16(v - __bfloat162float(hv));
        int e = o * 64 + (((ic >> 3) ^ (o & 7)) << 3) + (ic & 7);
        gw[b * 73728 + tap * 8192 + e]        = hv;
        gw[b * 73728 + tap * 8192 + 4096 + e] = lv;
    }
}

// ---------------------------------------------------------------------------
// Persistent mma.sync conv: 148 CTAs = 4 batch x 37; weights resident in smem.
// Tile = 16x8 pixels, all 64 oc. 8 warps: warp w -> M=64, N=16 (n8 tiles 2w,2w+1).
// K = 9 taps x 4 k16 chunks; 3 bf16 split terms per k-step.
// ---------------------------------------------------------------------------
template <int PASS>
__global__ void __launch_bounds__(256, 1)
conv_mma(const float* __restrict__ xin,
         const float* __restrict__ bias_g,
         float* __restrict__ xout) {
    extern __shared__ char smem[];
    const float* src = (PASS == 0) ? xin : g_mid;
    float*       dst = (PASS == 0) ? g_mid : xout;
    const __nv_bfloat16* wsrc = (PASS == 0) ? g_wA0 : g_wA1;

    const int tid = threadIdx.x, wrp = tid >> 5, lane = tid & 31;
    const int cta = blockIdx.x;
    const int b = cta / 37, i37 = cta % 37;
    const int t0 = (2048 * i37) / 37, t1 = (2048 * (i37 + 1)) / 37;
    const uint32_t sb = smem_u32(smem);

    // Weights: one 147456B copy per CTA lifetime (L2-resident source)
    {
        const uint4* wsv = (const uint4*)(wsrc + (size_t)b * 73728);
        uint4* wdv = (uint4*)smem;
        for (int i = tid; i < W_B / 16; i += 256) wdv[i] = wsv[i];
    }

    const size_t plane = (size_t)H * Wd;
    const float* srcb = src + (size_t)b * C * plane;
    float*       dstb = dst + (size_t)b * C * plane;

    const int g  = lane >> 2;      // B: pixel-in-n8 ; D: oc row offset
    const int t4 = lane & 3;       // B: k pair      ; D: pixel pair
    // A-fragment ldmatrix lane constants
    const int arow = lane & 15, aku = lane >> 4, asw = arow & 7;
    const uint32_t abase = sb + (uint32_t)(arow * 128);

    // bias per (mf, h)
    float biasv[4][2];
    #pragma unroll
    for (int mf = 0; mf < 4; ++mf)
        #pragma unroll
        for (int h = 0; h < 2; ++h)
            biasv[mf][h] = bias_g[mf * 16 + g + h * 8];

    const float gain = 1.4142135623730951f;

    for (int tix = t0; tix < t1; ++tix) {
        __syncthreads();   // previous tile's smem reads done (also covers W copy)
        const int by = tix >> 5, bx = tix & 31;
        const int y0 = by * TILE_H, x0 = bx * TILE_W;

        // ---- load input halo (10x18 x 64ic), bf16 hi/lo, padded-ic layout ----
        for (int idx = tid; idx < C * HALO_H * HALO_W; idx += 256) {
            int ic  = idx / 180;
            int rem = idx - ic * 180;
            int r   = rem / 18;
            int cc  = rem - r * 18;
            int gy = refl(y0 - 1 + r);
            int gx = refl(x0 - 1 + cc);
            float v = __ldg(srcb + (size_t)ic * plane + (size_t)gy * Wd + gx);
            __nv_bfloat16 hv = __float2bfloat16(v);
            __nv_bfloat16 lv = __float2bfloat16(v - __bfloat162float(hv));
            uint32_t off = (uint32_t)((r * 18 + cc) * PXB + ic * 2);
            *(__nv_bfloat16*)(smem + XHI_OFF + off) = hv;
            *(__nv_bfloat16*)(smem + XLO_OFF + off) = lv;
        }
        __syncthreads();

        float acc[4][2][4];
        #pragma unroll
        for (int mf = 0; mf < 4; ++mf)
            #pragma unroll
            for (int nt = 0; nt < 2; ++nt)
                #pragma unroll
                for (int q = 0; q < 4; ++q) acc[mf][nt][q] = 0.f;

        #pragma unroll 1
        for (int tap = 0; tap < 9; ++tap) {
            const int ky = tap / 3;
            const int kx = tap - 3 * ky;
            #pragma unroll
            for (int ks = 0; ks < 4; ++ks) {
                // A fragments: hi at tap*16384, lo at +8192; mf stride 2048
                uint32_t Ahi[4][4], Alo[4][4];
                uint32_t ah = abase + (uint32_t)(tap * 16384) +
                              (uint32_t)(((((ks << 1) | aku)) ^ asw) << 4);
                #pragma unroll
                for (int mf = 0; mf < 4; ++mf) {
                    ldmA(Ahi[mf], ah + mf * 2048);
                    ldmA(Alo[mf], ah + 8192 + mf * 2048);
                }
                // B fragments (plain LDS.32; pad-68 layout kills conflicts)
                uint32_t bh[2][2], bl[2][2];
                #pragma unroll
                for (int nt = 0; nt < 2; ++nt) {
                    int p  = (wrp * 2 + nt) * 8 + g;
                    int ir = (p >> 4) + ky;
                    int icx = (p & 15) + kx;
                    const char* ba = smem + XHI_OFF +
                                     (ir * 18 + icx) * PXB + ks * 32 + t4 * 4;
                    bh[nt][0] = *(const uint32_t*)(ba);
                    bh[nt][1] = *(const uint32_t*)(ba + 16);
                    bl[nt][0] = *(const uint32_t*)(ba + XTILE_B);
                    bl[nt][1] = *(const uint32_t*)(ba + XTILE_B + 16);
                }
                #pragma unroll
                for (int mf = 0; mf < 4; ++mf)
                    #pragma unroll
                    for (int nt = 0; nt < 2; ++nt) {
                        mma16816(acc[mf][nt], Ahi[mf], bh[nt][0], bh[nt][1]);
                        mma16816(acc[mf][nt], Ahi[mf], bl[nt][0], bl[nt][1]);
                        mma16816(acc[mf][nt], Alo[mf], bh[nt][0], bh[nt][1]);
                    }
            }
        }

        // ---- epilogue: bias + leakyrelu*sqrt2, float2 stores ----
        #pragma unroll
        for (int mf = 0; mf < 4; ++mf)
            #pragma unroll
            for (int nt = 0; nt < 2; ++nt)
                #pragma unroll
                for (int h = 0; h < 2; ++h) {
                    int oc = mf * 16 + g + h * 8;
                    int p0 = (wrp * 2 + nt) * 8 + 2 * t4;
                    int pr = p0 >> 4, pc = p0 & 15;
                    float v0 = acc[mf][nt][h * 2 + 0] + biasv[mf][h];
                    float v1 = acc[mf][nt][h * 2 + 1] + biasv[mf][h];
                    v0 = (v0 >= 0.f ? v0 : 0.2f * v0) * gain;
                    v1 = (v1 >= 0.f ? v1 : 0.2f * v1) * gain;
                    float2* dp = (float2*)(dstb + (size_t)oc * plane +
                                           (size_t)(y0 + pr) * Wd + x0 + pc);
                    *dp = make_float2(v0, v1);
                }
    }
}

extern "C" void kernel_launch(void* const* d_in, const int* in_sizes, int n_in,
                              void* d_out, int out_size) {
    const float* x      = (const float*)d_in[0];
    const float* latent = (const float*)d_in[1];
    const float* w0     = (const float*)d_in[2];
    const float* b0     = (const float*)d_in[3];
    const float* mw0    = (const float*)d_in[4];
    const float* mb0    = (const float*)d_in[5];
    const float* w1     = (const float*)d_in[6];
    const float* b1     = (const float*)d_in[7];
    const float* mw1    = (const float*)d_in[8];
    const float* mb1    = (const float*)d_in[9];
    float* out = (float*)d_out;

    cudaFuncSetAttribute(conv_mma<0>, cudaFuncAttributeMaxDynamicSharedMemorySize, SMEM_SZ);
    cudaFuncSetAttribute(conv_mma<1>, cudaFuncAttributeMaxDynamicSharedMemorySize, SMEM_SZ);

    prep_kernel<0><<<BATCH, 256>>>(latent, w0, mw0, mb0);
    prep_kernel<1><<<BATCH, 256>>>(latent, w1, mw1, mb1);

    conv_mma<0><<<148, 256, SMEM_SZ>>>(x, b0, out);
    conv_mma<1><<<148, 256, SMEM_SZ>>>(x, b1, out);
}

// round 8
// speedup vs baseline: 2.3859x; 1.1478x over previous
#include <cuda_runtime.h>
#include <cuda_bf16.h>
#include <cstdint>
#include <cstddef>

#define BATCH 4
#define C     64
#define H     512
#define Wd    512
#define LAT   256

#define TILE_W 16
#define TILE_H 8
#define HALO_W 18
#define HALO_H 10
#define NPX    (HALO_W * HALO_H)        // 180
#define PXB    144                      // padded bytes per pixel (64 bf16 + 16B pad)
#define XTILE_B (NPX * PXB)             // 25920
#define W_B     147456                  // 9 taps * 2 terms * 64oc * 128B
#define XHI_OFF W_B
#define XLO_OFF (W_B + XTILE_B)
#define SMEM_SZ (W_B + 2 * XTILE_B)     // 199296

// Scratch
__device__ __nv_bfloat16 g_wA0[BATCH * 73728];   // pre-swizzled hi/lo weights
__device__ __nv_bfloat16 g_wA1[BATCH * 73728];
__device__ float g_mid[(size_t)BATCH * C * H * Wd];

__device__ __forceinline__ int refl(int v) {
    return v < 0 ? -v : (v > H - 1 ? 2 * (H - 1) - v : v);
}
__device__ __forceinline__ uint32_t smem_u32(const void* p) {
    uint32_t a;
    asm("{ .reg .u64 t; cvta.to.shared.u64 t, %1; cvt.u32.u64 %0, t; }" : "=r"(a) : "l"(p));
    return a;
}
__device__ __forceinline__ void ldmA(uint32_t* r, uint32_t addr) {
    asm volatile("ldmatrix.sync.aligned.m8n8.x4.shared.b16 {%0,%1,%2,%3}, [%4];"
                 : "=r"(r[0]), "=r"(r[1]), "=r"(r[2]), "=r"(r[3]) : "r"(addr));
}
__device__ __forceinline__ void mma16816(float* c, const uint32_t* a,
                                         uint32_t b0, uint32_t b1) {
    asm volatile("mma.sync.aligned.m16n8k16.row.col.f32.bf16.bf16.f32 "
                 "{%0,%1,%2,%3},{%4,%5,%6,%7},{%8,%9},{%0,%1,%2,%3};"
                 : "+f"(c[0]), "+f"(c[1]), "+f"(c[2]), "+f"(c[3])
                 : "r"(a[0]), "r"(a[1]), "r"(a[2]), "r"(a[3]), "r"(b0), "r"(b1));
}

// ---------------------------------------------------------------------------
// Prep: fold modulation + demod; emit bf16 hi/lo in ldmatrix-swizzled layout.
// Per batch: per tap, hi tile (4096 bf16) then lo tile; tile elem(oc, ic) at
// oc*64 + (((ic>>3) ^ (oc&7))*8) + (ic&7).
// ---------------------------------------------------------------------------
template <int PASS>
__global__ void prep_kernel(const float* __restrict__ latent,
                            const float* __restrict__ w,
                            const float* __restrict__ mw,
                            const float* __restrict__ mb) {
    __nv_bfloat16* gw = (PASS == 0) ? g_wA0 : g_wA1;
    __shared__ float s[C];
    __shared__ float d[C];
    const int b = blockIdx.x;
    const int t = threadIdx.x;
    const float lscale = 0.08838834764831845f;   // sqrt(2/256)
    const float wscale = 0.05892556509887896f;   // sqrt(2/576)

    if (t < C) {
        float acc = 0.f;
        const float* lb  = latent + b * LAT;
        const float* mwr = mw + t * LAT;
        #pragma unroll 4
        for (int l = 0; l < LAT; ++l) acc += lb[l] * mwr[l];
        s[t] = 1.f + acc * lscale + mb[t];
    }
    __syncthreads();
    if (t < C) {
        float acc = 0.f;
        for (int i = 0; i < C; ++i) {
            float wsq = 0.f;
            const float* wr = w + (t * C + i) * 9;
            #pragma unroll
            for (int k = 0; k < 9; ++k) { float v = wr[k]; wsq += v * v; }
            acc += s[i] * s[i] * wsq;
        }
        d[t] = rsqrtf(acc * wscale * wscale + 1e-5f);
    }
    __syncthreads();
    for (int idx = t; idx < 9 * 64 * 64; idx += blockDim.x) {
        int ic  = idx & 63;
        int o   = (idx >> 6) & 63;
        int tap = idx >> 12;
        float v = d[o] * s[ic] * w[(o * 64 + ic) * 9 + tap] * wscale;
        __nv_bfloat16 hv = __float2bfloat16(v);
        __nv_bfloat16 lv = __float2bfloat16(v - __bfloat162float(hv));
        int e = o * 64 + (((ic >> 3) ^ (o & 7)) << 3) + (ic & 7);
        gw[b * 73728 + tap * 8192 + e]        = hv;
        gw[b * 73728 + tap * 8192 + 4096 + e] = lv;
    }
}

// ---------------------------------------------------------------------------
// Persistent mma.sync conv: 148 CTAs = 4 batch x 37; weights resident in smem.
// Tile = 16x8 pixels, all 64 oc. Warp tile M32 x N32:
//   ocg = wid&1 (oc 32), pxg = wid>>1 (32 pixels = 4 n8-groups).
// K = 9 taps x 4 k16 chunks; 3 bf16 split terms per k-step.
// ---------------------------------------------------------------------------
template <int PASS>
__global__ void __launch_bounds__(256, 1)
conv_mma(const float* __restrict__ xin,
         const float* __restrict__ bias_g,
         float* __restrict__ xout) {
    extern __shared__ char smem[];
    const float* src = (PASS == 0) ? xin : g_mid;
    float*       dst = (PASS == 0) ? g_mid : xout;
    const __nv_bfloat16* wsrc = (PASS == 0) ? g_wA0 : g_wA1;

    const int tid = threadIdx.x, wrp = tid >> 5, lane = tid & 31;
    const int cta = blockIdx.x;
    const int b = cta / 37, i37 = cta % 37;
    const int t0 = (2048 * i37) / 37, t1 = (2048 * (i37 + 1)) / 37;
    const uint32_t sb = smem_u32(smem);

    const int ocg = wrp & 1;       // 0/1 -> oc [ocg*32, +32)
    const int pxg = wrp >> 1;      // 0..3 -> pixels [pxg*32, +32)

    // Weights: one 147456B copy per CTA lifetime (L2-resident source)
    {
        const uint4* wsv = (const uint4*)(wsrc + (size_t)b * 73728);
        uint4* wdv = (uint4*)smem;
        for (int i = tid; i < W_B / 16; i += 256) wdv[i] = wsv[i];
    }

    const size_t plane = (size_t)H * Wd;
    const float* srcb = src + (size_t)b * C * plane;
    float*       dstb = dst + (size_t)b * C * plane;

    const int g  = lane >> 2;      // B: pixel-in-n8 ; D: oc row offset
    const int t4 = lane & 3;       // B: k pair      ; D: pixel pair
    const int arow = lane & 15, aku = lane >> 4, asw = arow & 7;
    const uint32_t abase = sb + (uint32_t)(ocg * 4096 + arow * 128);

    float biasv[2][2];
    #pragma unroll
    for (int mf = 0; mf < 2; ++mf)
        #pragma unroll
        for (int h = 0; h < 2; ++h)
            biasv[mf][h] = bias_g[ocg * 32 + mf * 16 + g + h * 8];

    const float gain = 1.4142135623730951f;

    for (int tix = t0; tix < t1; ++tix) {
        __syncthreads();   // previous tile's smem reads done (also covers W copy)
        const int by = tix >> 5, bx = tix & 31;
        const int y0 = by * TILE_H, x0 = bx * TILE_W;

        // ---- halo load: 180 px x 32 ic-pairs; lane group = 4 px x 8 icp ----
        for (int item = tid; item < NPX * 32; item += 256) {
            int tq  = item >> 3;                 // 0..719
            int px  = tq % NPX;
            int icp = ((tq / NPX) << 3) | (item & 7);   // 0..31
            int r  = px / 18, cc = px - r * 18;
            int gy = refl(y0 - 1 + r);
            int gx = refl(x0 - 1 + cc);
            const float* pp = srcb + (size_t)(2 * icp) * plane + (size_t)gy * Wd + gx;
            float f0 = pp[0];
            float f1 = pp[plane];
            __nv_bfloat162 hv;
            hv.x = __float2bfloat16(f0);
            hv.y = __float2bfloat16(f1);
            __nv_bfloat162 lv;
            lv.x = __float2bfloat16(f0 - __bfloat162float(hv.x));
            lv.y = __float2bfloat16(f1 - __bfloat162float(hv.y));
            uint32_t off = (uint32_t)(px * PXB + icp * 4);
            *(uint32_t*)(smem + XHI_OFF + off) = *(uint32_t*)&hv;
            *(uint32_t*)(smem + XLO_OFF + off) = *(uint32_t*)&lv;
        }
        __syncthreads();

        float acc[2][4][4];
        #pragma unroll
        for (int mf = 0; mf < 2; ++mf)
            #pragma unroll
            for (int nt = 0; nt < 4; ++nt)
                #pragma unroll
                for (int q = 0; q < 4; ++q) acc[mf][nt][q] = 0.f;

        #pragma unroll 1
        for (int tap = 0; tap < 9; ++tap) {
            const int ky = tap / 3;
            const int kx = tap - 3 * ky;
            #pragma unroll
            for (int ks = 0; ks < 4; ++ks) {
                // A fragments: hi at tap*16384, lo at +8192; mf stride 2048
                uint32_t Ahi[2][4], Alo[2][4];
                uint32_t ah = abase + (uint32_t)(tap * 16384) +
                              (uint32_t)((((ks << 1) | aku) ^ asw) << 4);
                #pragma unroll
                for (int mf = 0; mf < 2; ++mf) {
                    ldmA(Ahi[mf], ah + mf * 2048);
                    ldmA(Alo[mf], ah + 8192 + mf * 2048);
                }
                #pragma unroll
                for (int nt = 0; nt < 4; ++nt) {
                    int p   = pxg * 32 + nt * 8 + g;
                    int ir  = (p >> 4) + ky;
                    int icx = (p & 15) + kx;
                    const char* ba = smem + XHI_OFF +
                                     (ir * 18 + icx) * PXB + ks * 32 + t4 * 4;
                    uint32_t bh0 = *(const uint32_t*)(ba);
                    uint32_t bh1 = *(const uint32_t*)(ba + 16);
                    uint32_t bl0 = *(const uint32_t*)(ba + XTILE_B);
                    uint32_t bl1 = *(const uint32_t*)(ba + XTILE_B + 16);
                    #pragma unroll
                    for (int mf = 0; mf < 2; ++mf) {
                        mma16816(acc[mf][nt], Ahi[mf], bh0, bh1);
                        mma16816(acc[mf][nt], Ahi[mf], bl0, bl1);
                        mma16816(acc[mf][nt], Alo[mf], bh0, bh1);
                    }
                }
            }
        }

        // ---- epilogue: bias + leakyrelu*sqrt2, float2 stores ----
        #pragma unroll
        for (int mf = 0; mf < 2; ++mf)
            #pragma unroll
            for (int nt = 0; nt < 4; ++nt)
                #pragma unroll
                for (int h = 0; h < 2; ++h) {
                    int oc = ocg * 32 + mf * 16 + g + h * 8;
                    int p0 = pxg * 32 + nt * 8 + 2 * t4;
                    int pr = p0 >> 4, pc = p0 & 15;
                    float v0 = acc[mf][nt][h * 2 + 0] + biasv[mf][h];
                    float v1 = acc[mf][nt][h * 2 + 1] + biasv[mf][h];
                    v0 = (v0 >= 0.f ? v0 : 0.2f * v0) * gain;
                    v1 = (v1 >= 0.f ? v1 : 0.2f * v1) * gain;
                    float2* dp = (float2*)(dstb + (size_t)oc * plane +
                                           (size_t)(y0 + pr) * Wd + x0 + pc);
                    *dp = make_float2(v0, v1);
                }
    }
}

extern "C" void kernel_launch(void* const* d_in, const int* in_sizes, int n_in,
                              void* d_out, int out_size) {
    const float* x      = (const float*)d_in[0];
    const float* latent = (const float*)d_in[1];
    const float* w0     = (const float*)d_in[2];
    const float* b0     = (const float*)d_in[3];
    const float* mw0    = (const float*)d_in[4];
    const float* mb0    = (const float*)d_in[5];
    const float* w1     = (const float*)d_in[6];
    const float* b1     = (const float*)d_in[7];
    const float* mw1    = (const float*)d_in[8];
    const float* mb1    = (const float*)d_in[9];
    float* out = (float*)d_out;

    cudaFuncSetAttribute(conv_mma<0>, cudaFuncAttributeMaxDynamicSharedMemorySize, SMEM_SZ);
    cudaFuncSetAttribute(conv_mma<1>, cudaFuncAttributeMaxDynamicSharedMemorySize, SMEM_SZ);

    prep_kernel<0><<<BATCH, 256>>>(latent, w0, mw0, mb0);
    prep_kernel<1><<<BATCH, 256>>>(latent, w1, mw1, mb1);

    conv_mma<0><<<148, 256, SMEM_SZ>>>(x, b0, out);
    conv_mma<1><<<148, 256, SMEM_SZ>>>(x, b1, out);
}

// round 10
// speedup vs baseline: 4.1012x; 1.7189x over previous
#include <cuda_runtime.h>
#include <cuda_fp16.h>
#include <cstdint>
#include <cstddef>

#define BATCH 4
#define C     64
#define H     512
#define Wd    512
#define LAT   256

#define TILE_W 16
#define TILE_H 8
#define NPX    180                      // 18 x 10 halo pixels
#define PXB    144                      // bytes per halo pixel (128B data + 16B pad)
#define XTILE_B (NPX * PXB)             // 25920
#define W_B     147456                  // 9 taps * 2 terms * 64oc * 128B
#define XOFF    W_B
#define STG_OFF (W_B + 2 * XTILE_B)     // 199296
#define STG_B   18432                   // 128 px * 144B
#define SMEM_SZ (STG_OFF + STG_B)       // 217728 <= 232448

// Scratch
__device__ __half g_wA0[BATCH * 73728];     // fp16 hi + scaled-lo weights, swizzled
__device__ __half g_wA1[BATCH * 73728];
__device__ __half g_xh [(size_t)BATCH * H * Wd * C];  // input, NHWC fp16
__device__ __half g_mid[(size_t)BATCH * H * Wd * C];  // mid, NHWC fp16

__device__ __forceinline__ int refl(int v) {
    return v < 0 ? -v : (v > H - 1 ? 2 * (H - 1) - v : v);
}
__device__ __forceinline__ uint32_t smem_u32(const void* p) {
    uint32_t a;
    asm("{ .reg .u64 t; cvta.to.shared.u64 t, %1; cvt.u32.u64 %0, t; }" : "=r"(a) : "l"(p));
    return a;
}
__device__ __forceinline__ void ldmA(uint32_t* r, uint32_t addr) {
    asm volatile("ldmatrix.sync.aligned.m8n8.x4.shared.b16 {%0,%1,%2,%3}, [%4];"
                 : "=r"(r[0]), "=r"(r[1]), "=r"(r[2]), "=r"(r[3]) : "r"(addr));
}
__device__ __forceinline__ void mmaF(float* c, const uint32_t* a, uint32_t b0, uint32_t b1) {
    asm volatile("mma.sync.aligned.m16n8k16.row.col.f32.f16.f16.f32 "
                 "{%0,%1,%2,%3},{%4,%5,%6,%7},{%8,%9},{%0,%1,%2,%3};"
                 : "+f"(c[0]), "+f"(c[1]), "+f"(c[2]), "+f"(c[3])
                 : "r"(a[0]), "r"(a[1]), "r"(a[2]), "r"(a[3]), "r"(b0), "r"(b1));
}
__device__ __forceinline__ void mmaH(uint32_t* c, const uint32_t* a, uint32_t b0, uint32_t b1) {
    asm volatile("mma.sync.aligned.m16n8k16.row.col.f16.f16.f16.f16 "
                 "{%0,%1},{%2,%3,%4,%5},{%6,%7},{%0,%1};"
                 : "+r"(c[0]), "+r"(c[1])
                 : "r"(a[0]), "r"(a[1]), "r"(a[2]), "r"(a[3]), "r"(b0), "r"(b1));
}
__device__ __forceinline__ void cpa16(uint32_t ds, const void* gp) {
    asm volatile("cp.async.cg.shared.global [%0], [%1], 16;" :: "r"(ds), "l"(gp) : "memory");
}

// ---------------------------------------------------------------------------
// Input convert: NCHW fp32 -> NHWC fp16 (smem transpose, coalesced both ways)
// ---------------------------------------------------------------------------
__global__ void __launch_bounds__(256) xcvt(const float* __restrict__ x) {
    __shared__ __align__(16) __half st[32 * 72];
    const int b = blockIdx.z, y = blockIdx.y, x0 = blockIdx.x * 32;
    const int t = threadIdx.x;
    for (int i = t; i < 2048; i += 256) {
        int c = i >> 5, xx = i & 31;
        st[xx * 72 + c] =
            __float2half_rn(x[(((size_t)b * 64 + c) * 512 + y) * 512 + x0 + xx]);
    }
    __syncthreads();
    int px = t >> 3, ch = t & 7;
    uint4 v = *(const uint4*)&st[px * 72 + ch * 8];
    *(uint4*)&g_xh[(((size_t)b * 512 + y) * 512 + x0 + px) * 64 + ch * 8] = v;
}

// ---------------------------------------------------------------------------
// Prep: fold modulation + demod; emit fp16 hi + (lo * 2^12) in swizzled layout.
// Per batch per tap: hi tile (4096 halfs) then lo tile; elem(oc,ic) at
// oc*64 + (((ic>>3) ^ (oc&7))*8) + (ic&7).
// ---------------------------------------------------------------------------
template <int PASS>
__global__ void prep_kernel(const float* __restrict__ latent,
                            const float* __restrict__ w,
                            const float* __restrict__ mw,
                            const float* __restrict__ mb) {
    __half* gw = (PASS == 0) ? g_wA0 : g_wA1;
    __shared__ float s[C];
    __shared__ float d[C];
    const int b = blockIdx.x;
    const int t = threadIdx.x;
    const float lscale = 0.08838834764831845f;   // sqrt(2/256)
    const float wscale = 0.05892556509887896f;   // sqrt(2/576)

    if (t < C) {
        float acc = 0.f;
        const float* lb  = latent + b * LAT;
        const float* mwr = mw + t * LAT;
        #pragma unroll 4
        for (int l = 0; l < LAT; ++l) acc += lb[l] * mwr[l];
        s[t] = 1.f + acc * lscale + mb[t];
    }
    __syncthreads();
    if (t < C) {
        float acc = 0.f;
        for (int i = 0; i < C; ++i) {
            float wsq = 0.f;
            const float* wr = w + (t * C + i) * 9;
            #pragma unroll
            for (int k = 0; k < 9; ++k) { float v = wr[k]; wsq += v * v; }
            acc += s[i] * s[i] * wsq;
        }
        d[t] = rsqrtf(acc * wscale * wscale + 1e-5f);
    }
    __syncthreads();
    for (int idx = t; idx < 9 * 64 * 64; idx += blockDim.x) {
        int ic  = idx & 63;
        int o   = (idx >> 6) & 63;
        int tap = idx >> 12;
        float v = d[o] * s[ic] * w[(o * 64 + ic) * 9 + tap] * wscale;
        __half hv = __float2half_rn(v);
        __half lv = __float2half_rn((v - __half2float(hv)) * 4096.0f);
        int e = o * 64 + (((ic >> 3) ^ (o & 7)) << 3) + (ic & 7);
        gw[b * 73728 + tap * 8192 + e]        = hv;
        gw[b * 73728 + tap * 8192 + 4096 + e] = lv;
    }
}

// ---------------------------------------------------------------------------
// Persistent mma.sync conv. 148 CTAs = 4 batch x 37. Weights resident in smem.
// Tile = 16x8 px, all 64 oc. Warp tile M32 x N32 (ocg = wid&1, pxg = wid>>1).
// fp16 2-term: D = Whi*X (f32 acc) + 2^-12 * [Wlo'*X] (f16 acc).
// Halo: NHWC fp16 via cp.async, double-buffered (tile t+1 loads behind tile t).
// ---------------------------------------------------------------------------
template <int PASS>
__global__ void __launch_bounds__(256, 1)
conv_mma(const float* __restrict__ bias_g, float* __restrict__ xout) {
    extern __shared__ __align__(16) char smem[];
    const __half* src  = (PASS == 0) ? g_xh : g_mid;
    const __half* wsrc = (PASS == 0) ? g_wA0 : g_wA1;

    const int tid = threadIdx.x, wrp = tid >> 5, lane = tid & 31;
    const int cta = blockIdx.x;
    const int b = cta / 37, i37 = cta % 37;
    const int t0 = (2048 * i37) / 37, t1 = (2048 * (i37 + 1)) / 37;
    const uint32_t sb = smem_u32(smem);

    const int ocg = wrp & 1;
    const int pxg = wrp >> 1;

    // Weights: one copy per CTA lifetime
    {
        const uint4* wsv = (const uint4*)(wsrc + (size_t)b * 73728);
        uint4* wdv = (uint4*)smem;
        for (int i = tid; i < W_B / 16; i += 256) wdv[i] = wsv[i];
    }

    const __half* srcb = src + (size_t)b * (512 * 512 * 64);
    __half*       dsth = g_mid + (size_t)b * (512 * 512 * 64);
    const size_t plane = (size_t)H * Wd;
    float* dstf = xout + (size_t)b * C * plane;

    const int g  = lane >> 2;
    const int t4 = lane & 3;
    const int arow = lane & 15, aku = lane >> 4, asw = arow & 7;
    const uint32_t abase = sb + (uint32_t)(ocg * 4096 + arow * 128);

    float biasv[2][2];
    #pragma unroll
    for (int mf = 0; mf < 2; ++mf)
        #pragma unroll
        for (int h = 0; h < 2; ++h)
            biasv[mf][h] = bias_g[ocg * 32 + mf * 16 + g + h * 8];

    const float gain = 1.4142135623730951f;
    const float S = 2.44140625e-4f;   // 2^-12

    auto halo = [&](int tix, int bufsel) {
        const int y0 = (tix >> 5) * TILE_H, x0 = (tix & 31) * TILE_W;
        for (int item = tid; item < NPX * 8; item += 256) {
            int px = item >> 3, ch = item & 7;
            int r = px / 18, cc = px - r * 18;
            int gy = refl(y0 - 1 + r);
            int gx = refl(x0 - 1 + cc);
            const __half* gp = srcb + ((size_t)gy * 512 + gx) * 64 + ch * 8;
            uint32_t ds = sb + XOFF + (uint32_t)(bufsel * XTILE_B + px * PXB + ch * 16);
            cpa16(ds, gp);
        }
        asm volatile("cp.async.commit_group;" ::: "memory");
    };

    halo(t0, t0 & 1);

    for (int tix = t0; tix < t1; ++tix) {
        __syncthreads();   // prior tile fully consumed (smem X + stage)
        if (tix + 1 < t1) {
            halo(tix + 1, (tix + 1) & 1);
            asm volatile("cp.async.wait_group 1;" ::: "memory");
        } else {
            asm volatile("cp.async.wait_group 0;" ::: "memory");
        }
        __syncthreads();   // halo(tix) visible to all

        const int y0 = (tix >> 5) * TILE_H, x0 = (tix & 31) * TILE_W;
        const char* xb = smem + XOFF + (size_t)(tix & 1) * XTILE_B;

        float    acc [2][4][4];
        uint32_t accl[2][4][2];
        #pragma unroll
        for (int mf = 0; mf < 2; ++mf)
            #pragma unroll
            for (int nt = 0; nt < 4; ++nt) {
                #pragma unroll
                for (int q = 0; q < 4; ++q) acc[mf][nt][q] = 0.f;
                accl[mf][nt][0] = 0u; accl[mf][nt][1] = 0u;
            }

        #pragma unroll 1
        for (int tap = 0; tap < 9; ++tap) {
            const int ky = tap / 3;
            const int kx = tap - 3 * ky;
            #pragma unroll
            for (int ks = 0; ks < 4; ++ks) {
                uint32_t Ahi[2][4], Alo[2][4];
                uint32_t ah = abase + (uint32_t)(tap * 16384) +
                              (uint32_t)((((ks << 1) | aku) ^ asw) << 4);
                ldmA(Ahi[0], ah);
                ldmA(Ahi[1], ah + 2048);
                ldmA(Alo[0], ah + 8192);
                ldmA(Alo[1], ah + 8192 + 2048);
                #pragma unroll
                for (int nt = 0; nt < 4; ++nt) {
                    int p   = pxg * 32 + nt * 8 + g;
                    int ir  = (p >> 4) + ky;
                    int icx = (p & 15) + kx;
                    const char* ba = xb + (ir * 18 + icx) * PXB + ks * 32 + t4 * 4;
                    uint32_t b0 = *(const uint32_t*)(ba);
                    uint32_t b1 = *(const uint32_t*)(ba + 16);
                    mmaF(acc [0][nt], Ahi[0], b0, b1);
                    mmaF(acc [1][nt], Ahi[1], b0, b1);
                    mmaH(accl[0][nt], Alo[0], b0, b1);
                    mmaH(accl[1][nt], Alo[1], b0, b1);
                }
            }
        }

        // ---- epilogue ----
        #pragma unroll
        for (int mf = 0; mf < 2; ++mf)
            #pragma unroll
            for (int nt = 0; nt < 4; ++nt) {
                float2 l0 = __half22float2(*(const __half2*)&accl[mf][nt][0]);
                float2 l1 = __half22float2(*(const __half2*)&accl[mf][nt][1]);
                float v0 = acc[mf][nt][0] + S * l0.x + biasv[mf][0];
                float v1 = acc[mf][nt][1] + S * l0.y + biasv[mf][0];
                float v2 = acc[mf][nt][2] + S * l1.x + biasv[mf][1];
                float v3 = acc[mf][nt][3] + S * l1.y + biasv[mf][1];
                v0 = (v0 >= 0.f ? v0 : 0.2f * v0) * gain;
                v1 = (v1 >= 0.f ? v1 : 0.2f * v1) * gain;
                v2 = (v2 >= 0.f ? v2 : 0.2f * v2) * gain;
                v3 = (v3 >= 0.f ? v3 : 0.2f * v3) * gain;
                int px0 = pxg * 32 + nt * 8 + 2 * t4;
                if (PASS == 0) {
                    __half* stp = (__half*)(smem + STG_OFF);
                    int oc0 = ocg * 32 + mf * 16 + g;
                    stp[px0 * 72 + oc0]           = __float2half_rn(v0);
                    stp[(px0 + 1) * 72 + oc0]     = __float2half_rn(v1);
                    stp[px0 * 72 + oc0 + 8]       = __float2half_rn(v2);
                    stp[(px0 + 1) * 72 + oc0 + 8] = __float2half_rn(v3);
                } else {
                    int oc = ocg * 32 + mf * 16 + g;
                    int pr = px0 >> 4, pc = px0 & 15;
                    float* dp = dstf + (size_t)oc * plane + (size_t)(y0 + pr) * Wd + x0 + pc;
                    *(float2*)dp = make_float2(v0, v1);
                    *(float2*)(dp + 8 * plane) = make_float2(v2, v3);
                }
            }

        if (PASS == 0) {
            __syncthreads();
            int px = tid >> 1, hf = tid & 1;
            const uint4* sp = (const uint4*)(smem + STG_OFF + px * PXB + hf * 64);
            int gy = y0 + (px >> 4), gx = x0 + (px & 15);
            uint4* gp = (uint4*)(dsth + ((size_t)gy * 512 + gx) * 64 + hf * 32);
            gp[0] = sp[0]; gp[1] = sp[1]; gp[2] = sp[2]; gp[3] = sp[3];
        }
    }
}

extern "C" void kernel_launch(void* const* d_in, const int* in_sizes, int n_in,
                              void* d_out, int out_size) {
    const float* x      = (const float*)d_in[0];
    const float* latent = (const float*)d_in[1];
    const float* w0     = (const float*)d_in[2];
    const float* b0     = (const float*)d_in[3];
    const float* mw0    = (const float*)d_in[4];
    const float* mb0    = (const float*)d_in[5];
    const float* w1     = (const float*)d_in[6];
    const float* b1     = (const float*)d_in[7];
    const float* mw1    = (const float*)d_in[8];
    const float* mb1    = (const float*)d_in[9];
    float* out = (float*)d_out;

    cudaFuncSetAttribute(conv_mma<0>, cudaFuncAttributeMaxDynamicSharedMemorySize, SMEM_SZ);
    cudaFuncSetAttribute(conv_mma<1>, cudaFuncAttributeMaxDynamicSharedMemorySize, SMEM_SZ);

    xcvt<<<dim3(16, 512, 4), 256>>>(x);
    prep_kernel<0><<<BATCH, 256>>>(latent, w0, mw0, mb0);
    prep_kernel<1><<<BATCH, 256>>>(latent, w1, mw1, mb1);

    conv_mma<0><<<148, 256, SMEM_SZ>>>(b0, nullptr);
    conv_mma<1><<<148, 256, SMEM_SZ>>>(b1, out);
}

// round 11
// speedup vs baseline: 6.3360x; 1.5449x over previous
#include <cuda_runtime.h>
#include <cuda_fp16.h>
#include <cstdint>
#include <cstddef>

#define BATCH 4
#define C     64
#define H     512
#define Wd    512
#define LAT   256

#define TILE_W 16
#define TILE_H 16
#define HALO   18
#define NPX    (HALO * HALO)            // 324
#define PXB    160                      // bytes per halo pixel (128B data + 32B pad)
#define XTILE_B (NPX * PXB)             // 51840
#define W_B     73728                   // 9 taps * 64oc * 128B (fp16 hi only)
#define XOFF    W_B
#define STG_OFF (W_B + 2 * XTILE_B)     // 177408
#define STG_B   (256 * 144)             // 36864
#define SMEM_SZ (STG_OFF + STG_B)       // 214272 <= 232448

// Scratch
__device__ __half g_wA0[BATCH * 36864];     // fp16 weights, ldmatrix-swizzled
__device__ __half g_wA1[BATCH * 36864];
__device__ __half g_xh [(size_t)BATCH * H * Wd * C];  // input, NHWC fp16 (pair-permuted)
__device__ __half g_mid[(size_t)BATCH * H * Wd * C];  // mid, same layout

__device__ __forceinline__ int refl(int v) {
    return v < 0 ? -v : (v > H - 1 ? 2 * (H - 1) - v : v);
}
// channel -> permuted position: groups of 16; within group interleave pairs
// so that thread t4's 8B = channels {2t4, 2t4+1, 2t4+8, 2t4+9}.
__device__ __forceinline__ int ppos(int c) {
    int c16 = c & 15;
    return (c & ~15) + ((c16 >> 1) & 3) * 4 + ((c16 >> 3) & 1) * 2 + (c16 & 1);
}
__device__ __forceinline__ uint32_t smem_u32(const void* p) {
    uint32_t a;
    asm("{ .reg .u64 t; cvta.to.shared.u64 t, %1; cvt.u32.u64 %0, t; }" : "=r"(a) : "l"(p));
    return a;
}
__device__ __forceinline__ void ldmA(uint32_t* r, uint32_t addr) {
    asm volatile("ldmatrix.sync.aligned.m8n8.x4.shared.b16 {%0,%1,%2,%3}, [%4];"
                 : "=r"(r[0]), "=r"(r[1]), "=r"(r[2]), "=r"(r[3]) : "r"(addr));
}
__device__ __forceinline__ void mmaF(float* c, const uint32_t* a, uint32_t b0, uint32_t b1) {
    asm volatile("mma.sync.aligned.m16n8k16.row.col.f32.f16.f16.f32 "
                 "{%0,%1,%2,%3},{%4,%5,%6,%7},{%8,%9},{%0,%1,%2,%3};"
                 : "+f"(c[0]), "+f"(c[1]), "+f"(c[2]), "+f"(c[3])
                 : "r"(a[0]), "r"(a[1]), "r"(a[2]), "r"(a[3]), "r"(b0), "r"(b1));
}
__device__ __forceinline__ void cpa16(uint32_t ds, const void* gp) {
    asm volatile("cp.async.cg.shared.global [%0], [%1], 16;" :: "r"(ds), "l"(gp) : "memory");
}

// ---------------------------------------------------------------------------
// Input convert: NCHW fp32 -> NHWC fp16 pair-permuted. One block per (y, b).
// ---------------------------------------------------------------------------
__global__ void __launch_bounds__(256) xcvt(const float* __restrict__ x) {
    __shared__ __align__(16) __half st[32 * 72];
    const int y = blockIdx.x, b = blockIdx.y;
    const int t = threadIdx.x;
    for (int x0 = 0; x0 < 512; x0 += 32) {
        for (int i = t; i < 2048; i += 256) {
            int c = i >> 5, xx = i & 31;
            st[xx * 72 + ppos(c)] =
                __float2half_rn(x[(((size_t)b * 64 + c) * 512 + y) * 512 + x0 + xx]);
        }
        __syncthreads();
        int px = t >> 3, ch = t & 7;
        uint4 v = *(const uint4*)&st[px * 72 + ch * 8];
        *(uint4*)&g_xh[(((size_t)b * 512 + y) * 512 + x0 + px) * 64 + ch * 8] = v;
        __syncthreads();
    }
}

// ---------------------------------------------------------------------------
// Prep: fold modulation + demod; emit fp16 weights in ldmatrix-swizzled layout.
// Per batch per tap: 4096 halfs; elem(oc,ic) at oc*64 + (((ic>>3)^(oc&7))*8)+(ic&7).
// ---------------------------------------------------------------------------
template <int PASS>
__global__ void prep_kernel(const float* __restrict__ latent,
                            const float* __restrict__ w,
                            const float* __restrict__ mw,
                            const float* __restrict__ mb) {
    __half* gw = (PASS == 0) ? g_wA0 : g_wA1;
    __shared__ float s[C];
    __shared__ float d[C];
    const int b = blockIdx.x;
    const int t = threadIdx.x;
    const float lscale = 0.08838834764831845f;   // sqrt(2/256)
    const float wscale = 0.05892556509887896f;   // sqrt(2/576)

    if (t < C) {
        float acc = 0.f;
        const float* lb  = latent + b * LAT;
        const float* mwr = mw + t * LAT;
        #pragma unroll 4
        for (int l = 0; l < LAT; ++l) acc += lb[l] * mwr[l];
        s[t] = 1.f + acc * lscale + mb[t];
    }
    __syncthreads();
    if (t < C) {
        float acc = 0.f;
        for (int i = 0; i < C; ++i) {
            float wsq = 0.f;
            const float* wr = w + (t * C + i) * 9;
            #pragma unroll
            for (int k = 0; k < 9; ++k) { float v = wr[k]; wsq += v * v; }
            acc += s[i] * s[i] * wsq;
        }
        d[t] = rsqrtf(acc * wscale * wscale + 1e-5f);
    }
    __syncthreads();
    for (int idx = t; idx < 9 * 64 * 64; idx += blockDim.x) {
        int ic  = idx & 63;
        int o   = (idx >> 6) & 63;
        int tap = idx >> 12;
        float v = d[o] * s[ic] * w[(o * 64 + ic) * 9 + tap] * wscale;
        int e = o * 64 + (((ic >> 3) ^ (o & 7)) << 3) + (ic & 7);
        gw[b * 36864 + tap * 4096 + e] = __float2half_rn(v);
    }
}

// ---------------------------------------------------------------------------
// Persistent mma.sync conv. 148 CTAs = 4 batch x 37. fp16 weights in smem.
// Tile = 16x16 px, all 64 oc. Warp tile M32 x N64 (ocg = wid&1, pxg = wid>>1).
// Halo double-buffered via cp.async; B fragments = one conflict-free LDS.64.
// ---------------------------------------------------------------------------
template <int PASS>
__global__ void __launch_bounds__(256, 1)
conv_mma(const float* __restrict__ bias_g, float* __restrict__ xout) {
    extern __shared__ __align__(16) char smem[];
    const __half* src  = (PASS == 0) ? g_xh : g_mid;
    const __half* wsrc = (PASS == 0) ? g_wA0 : g_wA1;

    const int tid = threadIdx.x, wrp = tid >> 5, lane = tid & 31;
    const int cta = blockIdx.x;
    const int b = cta / 37, i37 = cta % 37;
    const int t0 = (1024 * i37) / 37, t1 = (1024 * (i37 + 1)) / 37;
    const uint32_t sb = smem_u32(smem);

    const int ocg = wrp & 1;       // oc group (32)
    const int pxg = wrp >> 1;      // 0..3 -> 64 pixels each

    // Weights: one 73728B copy per CTA lifetime
    {
        const uint4* wsv = (const uint4*)(wsrc + (size_t)b * 36864);
        uint4* wdv = (uint4*)smem;
        for (int i = tid; i < W_B / 16; i += 256) wdv[i] = wsv[i];
    }

    const __half* srcb = src + (size_t)b * (512 * 512 * 64);
    __half*       dsth = g_mid + (size_t)b * (512 * 512 * 64);
    const size_t plane = (size_t)H * Wd;
    float* dstf = xout + (size_t)b * C * plane;

    const int g  = lane >> 2;
    const int t4 = lane & 3;
    const int arow = lane & 15, aku = lane >> 4, asw = arow & 7;
    const uint32_t abase = sb + (uint32_t)(ocg * 4096 + arow * 128);

    float biasv[2][2];
    #pragma unroll
    for (int mf = 0; mf < 2; ++mf)
        #pragma unroll
        for (int h = 0; h < 2; ++h)
            biasv[mf][h] = bias_g[ocg * 32 + mf * 16 + g + h * 8];

    const float gain = 1.4142135623730951f;

    auto halo = [&](int tix, int bufsel) {
        const int y0 = (tix >> 5) * TILE_H, x0 = (tix & 31) * TILE_W;
        for (int item = tid; item < NPX * 8; item += 256) {
            int px = item >> 3, ch = item & 7;
            int r = px / HALO, cc = px - r * HALO;
            int gy = refl(y0 - 1 + r);
            int gx = refl(x0 - 1 + cc);
            const __half* gp = srcb + ((size_t)gy * 512 + gx) * 64 + ch * 8;
            uint32_t ds = sb + XOFF + (uint32_t)(bufsel * XTILE_B + px * PXB + ch * 16);
            cpa16(ds, gp);
        }
        asm volatile("cp.async.commit_group;" ::: "memory");
    };

    halo(t0, t0 & 1);

    for (int tix = t0; tix < t1; ++tix) {
        __syncthreads();   // prior tile fully consumed
        if (tix + 1 < t1) {
            halo(tix + 1, (tix + 1) & 1);
            asm volatile("cp.async.wait_group 1;" ::: "memory");
        } else {
            asm volatile("cp.async.wait_group 0;" ::: "memory");
        }
        __syncthreads();   // halo(tix) visible

        const int y0 = (tix >> 5) * TILE_H, x0 = (tix & 31) * TILE_W;
        const char* xb = smem + XOFF + (size_t)(tix & 1) * XTILE_B;

        float acc[2][8][4];
        #pragma unroll
        for (int mf = 0; mf < 2; ++mf)
            #pragma unroll
            for (int nt = 0; nt < 8; ++nt)
                #pragma unroll
                for (int q = 0; q < 4; ++q) acc[mf][nt][q] = 0.f;

        #pragma unroll 1
        for (int tap = 0; tap < 9; ++tap) {
            const int ky = tap / 3;
            const int kx = tap - 3 * ky;
            #pragma unroll
            for (int ks = 0; ks < 4; ++ks) {
                uint32_t A0[4], A1[4];
                uint32_t ah = abase + (uint32_t)(tap * 8192) +
                              (uint32_t)((((ks << 1) | aku) ^ asw) << 4);
                ldmA(A0, ah);
                ldmA(A1, ah + 2048);
                #pragma unroll
                for (int nt = 0; nt < 8; ++nt) {
                    int p   = pxg * 64 + nt * 8 + g;
                    int ir  = (p >> 4) + ky;
                    int icx = (p & 15) + kx;
                    const char* ba = xb + (ir * HALO + icx) * PXB + ks * 32 + t4 * 8;
                    uint2 bv = *(const uint2*)(ba);
                    mmaF(acc[0][nt], A0, bv.x, bv.y);
                    mmaF(acc[1][nt], A1, bv.x, bv.y);
                }
            }
        }

        // ---- epilogue ----
        #pragma unroll
        for (int mf = 0; mf < 2; ++mf)
            #pragma unroll
            for (int nt = 0; nt < 8; ++nt) {
                float v0 = acc[mf][nt][0] + biasv[mf][0];
                float v1 = acc[mf][nt][1] + biasv[mf][0];
                float v2 = acc[mf][nt][2] + biasv[mf][1];
                float v3 = acc[mf][nt][3] + biasv[mf][1];
                v0 = (v0 >= 0.f ? v0 : 0.2f * v0) * gain;
                v1 = (v1 >= 0.f ? v1 : 0.2f * v1) * gain;
                v2 = (v2 >= 0.f ? v2 : 0.2f * v2) * gain;
                v3 = (v3 >= 0.f ? v3 : 0.2f * v3) * gain;
                int px0 = pxg * 64 + nt * 8 + 2 * t4;
                if (PASS == 0) {
                    __half* stp = (__half*)(smem + STG_OFF);
                    int oc0 = ocg * 32 + mf * 16 + g;
                    int p0 = ppos(oc0);          // h=0 position
                    int p1 = ppos(oc0 + 8);      // h=1 position (= p0 + 2)
                    stp[px0 * 72 + p0]       = __float2half_rn(v0);
                    stp[(px0 + 1) * 72 + p0] = __float2half_rn(v1);
                    stp[px0 * 72 + p1]       = __float2half_rn(v2);
                    stp[(px0 + 1) * 72 + p1] = __float2half_rn(v3);
                } else {
                    int oc = ocg * 32 + mf * 16 + g;
                    int pr = px0 >> 4, pc = px0 & 15;
                    float* dp = dstf + (size_t)oc * plane + (size_t)(y0 + pr) * Wd + x0 + pc;
                    *(float2*)dp = make_float2(v0, v1);
                    *(float2*)(dp + 8 * plane) = make_float2(v2, v3);
                }
            }

        if (PASS == 0) {
            __syncthreads();
            int px = tid;
            const uint4* sp = (const uint4*)(smem + STG_OFF + px * 144);
            int gy = y0 + (px >> 4), gx = x0 + (px & 15);
            uint4* gp = (uint4*)(dsth + ((size_t)gy * 512 + gx) * 64);
            #pragma unroll
            for (int j = 0; j < 8; ++j) gp[j] = sp[j];
        }
    }
}

extern "C" void kernel_launch(void* const* d_in, const int* in_sizes, int n_in,
                              void* d_out, int out_size) {
    const float* x      = (const float*)d_in[0];
    const float* latent = (const float*)d_in[1];
    const float* w0     = (const float*)d_in[2];
    const float* b0     = (const float*)d_in[3];
    const float* mw0    = (const float*)d_in[4];
    const float* mb0    = (const float*)d_in[5];
    const float* w1     = (const float*)d_in[6];
    const float* b1     = (const float*)d_in[7];
    const float* mw1    = (const float*)d_in[8];
    const float* mb1    = (const float*)d_in[9];
    float* out = (float*)d_out;

    cudaFuncSetAttribute(conv_mma<0>, cudaFuncAttributeMaxDynamicSharedMemorySize, SMEM_SZ);
    cudaFuncSetAttribute(conv_mma<1>, cudaFuncAttributeMaxDynamicSharedMemorySize, SMEM_SZ);

    xcvt<<<dim3(512, 4), 256>>>(x);
    prep_kernel<0><<<BATCH, 256>>>(latent, w0, mw0, mb0);
    prep_kernel<1><<<BATCH, 256>>>(latent, w1, mw1, mb1);

    conv_mma<0><<<148, 256, SMEM_SZ>>>(b0, nullptr);
    conv_mma<1><<<148, 256, SMEM_SZ>>>(b1, out);
}

// round 12
// speedup vs baseline: 6.4565x; 1.0190x over previous
#include <cuda_runtime.h>
#include <cuda_fp16.h>
#include <cstdint>
#include <cstddef>

#define BATCH 4
#define C     64
#define H     512
#define Wd    512
#define LAT   256

#define TILE_W 16
#define TILE_H 16
#define HALO   18
#define NPX    (HALO * HALO)            // 324
#define PXB    176                      // bytes per halo pixel (128B data + 48B pad)
#define XTILE_B (NPX * PXB)             // 57024
#define W_B     73728                   // 9 taps * 64oc * 128B (fp16)
#define XOFF    W_B
#define STG_OFF (W_B + 2 * XTILE_B)     // 187776
#define STG_B   (256 * 144)             // 36864
#define SMEM_SZ (STG_OFF + STG_B)       // 224640 <= 232448

// Scratch
__device__ __half g_wA0[BATCH * 36864];     // fp16 weights, ldmatrix-swizzled
__device__ __half g_wA1[BATCH * 36864];
__device__ __half g_xh [(size_t)BATCH * H * Wd * C];  // input, NHWC fp16 (ppos2-permuted)
__device__ __half g_mid[(size_t)BATCH * H * Wd * C];  // mid, same layout

__device__ __forceinline__ int refl(int v) {
    return v < 0 ? -v : (v > H - 1 ? 2 * (H - 1) - v : v);
}
// channel -> permuted position so thread t4 owns a contiguous 32B block holding
// its B-fragment halves for all 4 k16 chunks:
//   pos = t4*16 + ks*4 + j ;  t4=(c>>1)&3, ks=c>>4, j=(c&1)|((c>>2)&2)
__device__ __forceinline__ int ppos2(int c) {
    return (((c >> 1) & 3) << 4) + ((c >> 4) << 2) + ((c & 1) | ((c >> 2) & 2));
}
__device__ __forceinline__ uint32_t smem_u32(const void* p) {
    uint32_t a;
    asm("{ .reg .u64 t; cvta.to.shared.u64 t, %1; cvt.u32.u64 %0, t; }" : "=r"(a) : "l"(p));
    return a;
}
__device__ __forceinline__ void ldmA(uint32_t* r, uint32_t addr) {
    asm volatile("ldmatrix.sync.aligned.m8n8.x4.shared.b16 {%0,%1,%2,%3}, [%4];"
                 : "=r"(r[0]), "=r"(r[1]), "=r"(r[2]), "=r"(r[3]) : "r"(addr));
}
__device__ __forceinline__ void mmaF(float* c, const uint32_t* a, uint32_t b0, uint32_t b1) {
    asm volatile("mma.sync.aligned.m16n8k16.row.col.f32.f16.f16.f32 "
                 "{%0,%1,%2,%3},{%4,%5,%6,%7},{%8,%9},{%0,%1,%2,%3};"
                 : "+f"(c[0]), "+f"(c[1]), "+f"(c[2]), "+f"(c[3])
                 : "r"(a[0]), "r"(a[1]), "r"(a[2]), "r"(a[3]), "r"(b0), "r"(b1));
}
__device__ __forceinline__ void cpa16(uint32_t ds, const void* gp) {
    asm volatile("cp.async.cg.shared.global [%0], [%1], 16;" :: "r"(ds), "l"(gp) : "memory");
}

// ---------------------------------------------------------------------------
// Input convert: NCHW fp32 -> NHWC fp16 ppos2-permuted. One block per (y, b).
// ---------------------------------------------------------------------------
__global__ void __launch_bounds__(256) xcvt(const float* __restrict__ x) {
    __shared__ __align__(16) __half st[32 * 72];
    const int y = blockIdx.x, b = blockIdx.y;
    const int t = threadIdx.x;
    for (int x0 = 0; x0 < 512; x0 += 32) {
        for (int i = t; i < 2048; i += 256) {
            int c = i >> 5, xx = i & 31;
            st[xx * 72 + ppos2(c)] =
                __float2half_rn(x[(((size_t)b * 64 + c) * 512 + y) * 512 + x0 + xx]);
        }
        __syncthreads();
        int px = t >> 3, ch = t & 7;
        uint4 v = *(const uint4*)&st[px * 72 + ch * 8];
        *(uint4*)&g_xh[(((size_t)b * 512 + y) * 512 + x0 + px) * 64 + ch * 8] = v;
        __syncthreads();
    }
}

// ---------------------------------------------------------------------------
// Prep (both passes): fold modulation + demod; emit fp16 weights swizzled for
// ldmatrix. blockIdx = (batch, pass). elem(oc,ic) at
// oc*64 + (((ic>>3)^(oc&7))*8) + (ic&7).
// ---------------------------------------------------------------------------
__global__ void prep_kernel(const float* __restrict__ latent,
                            const float* __restrict__ w0g,
                            const float* __restrict__ mw0g,
                            const float* __restrict__ mb0g,
                            const float* __restrict__ w1g,
                            const float* __restrict__ mw1g,
                            const float* __restrict__ mb1g) {
    const int pass = blockIdx.y;
    const float* w  = pass ? w1g  : w0g;
    const float* mw = pass ? mw1g : mw0g;
    const float* mb = pass ? mb1g : mb0g;
    __half* gw = pass ? g_wA1 : g_wA0;
    __shared__ float s[C];
    __shared__ float d[C];
    const int b = blockIdx.x;
    const int t = threadIdx.x;
    const float lscale = 0.08838834764831845f;   // sqrt(2/256)
    const float wscale = 0.05892556509887896f;   // sqrt(2/576)

    if (t < C) {
        float acc = 0.f;
        const float* lb  = latent + b * LAT;
        const float* mwr = mw + t * LAT;
        #pragma unroll 4
        for (int l = 0; l < LAT; ++l) acc += lb[l] * mwr[l];
        s[t] = 1.f + acc * lscale + mb[t];
    }
    __syncthreads();
    if (t < C) {
        float acc = 0.f;
        for (int i = 0; i < C; ++i) {
            float wsq = 0.f;
            const float* wr = w + (t * C + i) * 9;
            #pragma unroll
            for (int k = 0; k < 9; ++k) { float v = wr[k]; wsq += v * v; }
            acc += s[i] * s[i] * wsq;
        }
        d[t] = rsqrtf(acc * wscale * wscale + 1e-5f);
    }
    __syncthreads();
    for (int idx = t; idx < 9 * 64 * 64; idx += blockDim.x) {
        int ic  = idx & 63;
        int o   = (idx >> 6) & 63;
        int tap = idx >> 12;
        float v = d[o] * s[ic] * w[(o * 64 + ic) * 9 + tap] * wscale;
        int e = o * 64 + (((ic >> 3) ^ (o & 7)) << 3) + (ic & 7);
        gw[b * 36864 + tap * 4096 + e] = __float2half_rn(v);
    }
}

// ---------------------------------------------------------------------------
// Persistent mma.sync conv. 148 CTAs = 4 batch x 37. fp16 weights in smem.
// Tile = 16x16 px, all 64 oc. Warp tile M32 x N64 (ocg = wid&1, pxg = wid>>1).
// Per tap: 8 ldmatrix.x4 (A, all 4 k-chunks) + 16 LDS.128 (B) + 64 HMMA.
// Halo double-buffered via cp.async.
// ---------------------------------------------------------------------------
template <int PASS>
__global__ void __launch_bounds__(256, 1)
conv_mma(const float* __restrict__ bias_g, float* __restrict__ xout) {
    extern __shared__ __align__(16) char smem[];
    const __half* src  = (PASS == 0) ? g_xh : g_mid;
    const __half* wsrc = (PASS == 0) ? g_wA0 : g_wA1;

    const int tid = threadIdx.x, wrp = tid >> 5, lane = tid & 31;
    const int cta = blockIdx.x;
    const int b = cta / 37, i37 = cta % 37;
    const int t0 = (1024 * i37) / 37, t1 = (1024 * (i37 + 1)) / 37;
    const uint32_t sb = smem_u32(smem);

    const int ocg = wrp & 1;       // oc group (32)
    const int pxg = wrp >> 1;      // 0..3 -> 64 pixels each

    // Weights: one 73728B copy per CTA lifetime
    {
        const uint4* wsv = (const uint4*)(wsrc + (size_t)b * 36864);
        uint4* wdv = (uint4*)smem;
        for (int i = tid; i < W_B / 16; i += 256) wdv[i] = wsv[i];
    }

    const __half* srcb = src + (size_t)b * (512 * 512 * 64);
    __half*       dsth = g_mid + (size_t)b * (512 * 512 * 64);
    const size_t plane = (size_t)H * Wd;
    float* dstf = xout + (size_t)b * C * plane;

    const int g  = lane >> 2;
    const int t4 = lane & 3;
    const int arow = lane & 15, aku = lane >> 4, asw = arow & 7;
    const uint32_t abase = sb + (uint32_t)(ocg * 4096 + arow * 128);

    // loop-invariant B pixel bases
    int pixB[8];
    #pragma unroll
    for (int nt = 0; nt < 8; ++nt) {
        int p = pxg * 64 + nt * 8 + g;
        pixB[nt] = ((p >> 4) * HALO + (p & 15)) * PXB + t4 * 32;
    }

    float biasv[2][2];
    #pragma unroll
    for (int mf = 0; mf < 2; ++mf)
        #pragma unroll
        for (int h = 0; h < 2; ++h)
            biasv[mf][h] = bias_g[ocg * 32 + mf * 16 + g + h * 8];

    const float gain = 1.4142135623730951f;

    auto halo = [&](int tix, int bufsel) {
        const int y0 = (tix >> 5) * TILE_H, x0 = (tix & 31) * TILE_W;
        for (int item = tid; item < NPX * 8; item += 256) {
            int px = item >> 3, ch = item & 7;
            int r = px / HALO, cc = px - r * HALO;
            int gy = refl(y0 - 1 + r);
            int gx = refl(x0 - 1 + cc);
            const __half* gp = srcb + ((size_t)gy * 512 + gx) * 64 + ch * 8;
            uint32_t ds = sb + XOFF + (uint32_t)(bufsel * XTILE_B + px * PXB + ch * 16);
            cpa16(ds, gp);
        }
        asm volatile("cp.async.commit_group;" ::: "memory");
    };

    halo(t0, t0 & 1);

    for (int tix = t0; tix < t1; ++tix) {
        __syncthreads();   // prior tile fully consumed
        if (tix + 1 < t1) {
            halo(tix + 1, (tix + 1) & 1);
            asm volatile("cp.async.wait_group 1;" ::: "memory");
        } else {
            asm volatile("cp.async.wait_group 0;" ::: "memory");
        }
        __syncthreads();   // halo(tix) visible

        const int y0 = (tix >> 5) * TILE_H, x0 = (tix & 31) * TILE_W;
        const char* xb = smem + XOFF + (size_t)(tix & 1) * XTILE_B;

        float acc[2][8][4];
        #pragma unroll
        for (int mf = 0; mf < 2; ++mf)
            #pragma unroll
            for (int nt = 0; nt < 8; ++nt)
                #pragma unroll
                for (int q = 0; q < 4; ++q) acc[mf][nt][q] = 0.f;

        #pragma unroll 1
        for (int tap = 0; tap < 9; ++tap) {
            const int ky = tap / 3;
            const int kx = tap - 3 * ky;
            const int tapOff = (ky * HALO + kx) * PXB;

            uint32_t A0[4][4], A1[4][4];
            const uint32_t ah = abase + (uint32_t)(tap * 8192);
            #pragma unroll
            for (int ks = 0; ks < 4; ++ks) {
                uint32_t a = ah + (uint32_t)((((ks << 1) | aku) ^ asw) << 4);
                ldmA(A0[ks], a);
                ldmA(A1[ks], a + 2048);
            }
            #pragma unroll
            for (int nt = 0; nt < 8; ++nt) {
                const char* ba = xb + pixB[nt] + tapOff;
                uint4 q0 = *(const uint4*)(ba);
                uint4 q1 = *(const uint4*)(ba + 16);
                mmaF(acc[0][nt], A0[0], q0.x, q0.y);
                mmaF(acc[1][nt], A1[0], q0.x, q0.y);
                mmaF(acc[0][nt], A0[1], q0.z, q0.w);
                mmaF(acc[1][nt], A1[1], q0.z, q0.w);
                mmaF(acc[0][nt], A0[2], q1.x, q1.y);
                mmaF(acc[1][nt], A1[2], q1.x, q1.y);
                mmaF(acc[0][nt], A0[3], q1.z, q1.w);
                mmaF(acc[1][nt], A1[3], q1.z, q1.w);
            }
        }

        // ---- epilogue ----
        #pragma unroll
        for (int mf = 0; mf < 2; ++mf)
            #pragma unroll
            for (int nt = 0; nt < 8; ++nt) {
                float v0 = acc[mf][nt][0] + biasv[mf][0];
                float v1 = acc[mf][nt][1] + biasv[mf][0];
                float v2 = acc[mf][nt][2] + biasv[mf][1];
                float v3 = acc[mf][nt][3] + biasv[mf][1];
                v0 = (v0 >= 0.f ? v0 : 0.2f * v0) * gain;
                v1 = (v1 >= 0.f ? v1 : 0.2f * v1) * gain;
                v2 = (v2 >= 0.f ? v2 : 0.2f * v2) * gain;
                v3 = (v3 >= 0.f ? v3 : 0.2f * v3) * gain;
                int px0 = pxg * 64 + nt * 8 + 2 * t4;
                if (PASS == 0) {
                    __half* stp = (__half*)(smem + STG_OFF);
                    int oc0 = ocg * 32 + mf * 16 + g;
                    int p0 = ppos2(oc0);          // h=1 channel sits at p0+2
                    stp[px0 * 72 + p0]           = __float2half_rn(v0);
                    stp[(px0 + 1) * 72 + p0]     = __float2half_rn(v1);
                    stp[px0 * 72 + p0 + 2]       = __float2half_rn(v2);
                    stp[(px0 + 1) * 72 + p0 + 2] = __float2half_rn(v3);
                } else {
                    int oc = ocg * 32 + mf * 16 + g;
                    int pr = px0 >> 4, pc = px0 & 15;
                    float* dp = dstf + (size_t)oc * plane + (size_t)(y0 + pr) * Wd + x0 + pc;
                    *(float2*)dp = make_float2(v0, v1);
                    *(float2*)(dp + 8 * plane) = make_float2(v2, v3);
                }
            }

        if (PASS == 0) {
            __syncthreads();
            int px = tid;
            const uint4* sp = (const uint4*)(smem + STG_OFF + px * 144);
            int gy = y0 + (px >> 4), gx = x0 + (px & 15);
            uint4* gp = (uint4*)(dsth + ((size_t)gy * 512 + gx) * 64);
            #pragma unroll
            for (int j = 0; j < 8; ++j) gp[j] = sp[j];
        }
    }
}

extern "C" void kernel_launch(void* const* d_in, const int* in_sizes, int n_in,
                              void* d_out, int out_size) {
    const float* x      = (const float*)d_in[0];
    const float* latent = (const float*)d_in[1];
    const float* w0     = (const float*)d_in[2];
    const float* b0     = (const float*)d_in[3];
    const float* mw0    = (const float*)d_in[4];
    const float* mb0    = (const float*)d_in[5];
    const float* w1     = (const float*)d_in[6];
    const float* b1     = (const float*)d_in[7];
    const float* mw1    = (const float*)d_in[8];
    const float* mb1    = (const float*)d_in[9];
    float* out = (float*)d_out;

    cudaFuncSetAttribute(conv_mma<0>, cudaFuncAttributeMaxDynamicSharedMemorySize, SMEM_SZ);
    cudaFuncSetAttribute(conv_mma<1>, cudaFuncAttributeMaxDynamicSharedMemorySize, SMEM_SZ);

    xcvt<<<dim3(512, 4), 256>>>(x);
    prep_kernel<<<dim3(BATCH, 2), 256>>>(latent, w0, mw0, mb0, w1, mw1, mb1);

    conv_mma<0><<<148, 256, SMEM_SZ>>>(b0, nullptr);
    conv_mma<1><<<148, 256, SMEM_SZ>>>(b1, out);
}